// round 1
// baseline (speedup 1.0000x reference)
#include <cuda_runtime.h>
#include <cuda_bf16.h>
#include <math.h>

// ---------------- problem constants (fixed shapes per reference) -------------
#define N_NODES_C 100000
#define NR_C      10000
#define NRHO_C    10000
#define CUTOFF_C  6.0f
#define RHOMAX_C  60.0f

// ---------------- device scratch (static, allocation-free) ------------------
__device__ float  g_node_rho[N_NODES_C];
__device__ float  g_Fp[N_NODES_C];
__device__ double g_E;
__device__ float4 g_rad0[NR_C - 1];    // density channel: a,b,c,d
__device__ float4 g_rad1[NR_C - 1];    // rphi channel:    a,b,c,d
__device__ float4 g_emb[NRHO_C - 1];   // embedding:       a,b,c,d

// ---------------- helpers ----------------------------------------------------
__device__ __forceinline__ int spline_idx(float x, const float* __restrict__ knots,
                                          int K, float scale) {
    int idx = (int)(x * scale);
    idx = min(max(idx, 0), K - 2);
    float k0 = __ldg(knots + idx);
    if (x < k0) {
        if (idx > 0) idx--;
    } else if (idx < K - 2 && x >= __ldg(knots + idx + 1)) {
        idx++;
    }
    return idx;
}

__device__ __forceinline__ double block_reduce_d(double v) {
    __shared__ double sh[32];
    #pragma unroll
    for (int o = 16; o > 0; o >>= 1) v += __shfl_down_sync(0xffffffffu, v, o);
    int lane = threadIdx.x & 31, w = threadIdx.x >> 5;
    if (lane == 0) sh[w] = v;
    __syncthreads();
    int nw = blockDim.x >> 5;
    v = (threadIdx.x < nw) ? sh[threadIdx.x] : 0.0;
    if (w == 0) {
        #pragma unroll
        for (int o = 16; o > 0; o >>= 1) v += __shfl_down_sync(0xffffffffu, v, o);
    }
    return v;
}

// ---------------- kernels ----------------------------------------------------
__global__ void k_pack(const float* __restrict__ ra, const float* __restrict__ rb,
                       const float* __restrict__ rc, const float* __restrict__ rd,
                       const float* __restrict__ ea, const float* __restrict__ eb,
                       const float* __restrict__ ec, const float* __restrict__ ed) {
    int i = blockIdx.x * blockDim.x + threadIdx.x;
    if (i < NR_C - 1) {
        g_rad0[i] = make_float4(ra[2*i],   rb[2*i],   rc[2*i],   rd[2*i]);
        g_rad1[i] = make_float4(ra[2*i+1], rb[2*i+1], rc[2*i+1], rd[2*i+1]);
    }
    if (i < NRHO_C - 1) {
        g_emb[i] = make_float4(ea[i], eb[i], ec[i], ed[i]);
    }
}

__global__ void k_zero(float* __restrict__ out, int out_size) {
    int i = blockIdx.x * blockDim.x + threadIdx.x;
    if (i < out_size) out[i] = 0.0f;
    if (i < N_NODES_C) { g_node_rho[i] = 0.0f; g_Fp[i] = 0.0f; }
    if (i == 0) g_E = 0.0;
}

// Pass 1: per-edge density scatter + 0.5*sum(phi/r) into g_E
__global__ void k_edge_rho(const float* __restrict__ r,
                           const int* __restrict__ dst,
                           const float* __restrict__ rs,
                           int n_edges) {
    int e = blockIdx.x * blockDim.x + threadIdx.x;
    double part = 0.0;
    if (e < n_edges) {
        float x = r[3*e], y = r[3*e+1], z = r[3*e+2];
        float bl = sqrtf(x*x + y*y + z*z);
        int idx = spline_idx(bl, rs, NR_C, (float)(NR_C - 1) / CUTOFF_C);
        float s = bl - __ldg(rs + idx);
        float4 c0 = g_rad0[idx];
        float4 c1 = g_rad1[idx];
        float rho = c0.x + s * (c0.y + s * (c0.z + s * c0.w));
        float phi = c1.x + s * (c1.y + s * (c1.z + s * c1.w));
        atomicAdd(&g_node_rho[dst[e]], rho);
        part = 0.5 * (double)(phi / bl);
    }
    double tot = block_reduce_d(part);
    if (threadIdx.x == 0) atomicAdd(&g_E, tot);
}

// Pass 2: per-node embedding energy + derivative
__global__ void k_node(const float* __restrict__ rhos) {
    int n = blockIdx.x * blockDim.x + threadIdx.x;
    double part = 0.0;
    if (n < N_NODES_C) {
        float rho = g_node_rho[n];
        int idx = spline_idx(rho, rhos, NRHO_C, (float)(NRHO_C - 1) / RHOMAX_C);
        float s = rho - __ldg(rhos + idx);
        float4 c = g_emb[idx];
        float F  = c.x + s * (c.y + s * (c.z + s * c.w));
        float Fp = c.y + s * (2.0f * c.z + 3.0f * s * c.w);
        g_Fp[n] = Fp;
        part = (double)F;
    }
    double tot = block_reduce_d(part);
    if (threadIdx.x == 0) atomicAdd(&g_E, tot);
}

// Pass 3: per-edge force scatter (analytic gradient)
__global__ void k_edge_force(const float* __restrict__ r,
                             const int* __restrict__ src,
                             const int* __restrict__ dst,
                             const float* __restrict__ rs,
                             float* __restrict__ forces,   // d_out + 1
                             int n_edges) {
    int e = blockIdx.x * blockDim.x + threadIdx.x;
    if (e >= n_edges) return;
    float x = r[3*e], y = r[3*e+1], z = r[3*e+2];
    float bl = sqrtf(x*x + y*y + z*z);
    int idx = spline_idx(bl, rs, NR_C, (float)(NR_C - 1) / CUTOFF_C);
    float s = bl - __ldg(rs + idx);
    float4 c0 = g_rad0[idx];
    float4 c1 = g_rad1[idx];
    float rho_p = c0.y + s * (2.0f * c0.z + 3.0f * s * c0.w);
    float phi   = c1.x + s * (c1.y + s * (c1.z + s * c1.w));
    float phi_p = c1.y + s * (2.0f * c1.z + 3.0f * s * c1.w);
    int di = dst[e], si = src[e];
    float Fp = g_Fp[di];
    float inv = 1.0f / bl;
    // dE/du with u = bl
    float g = Fp * rho_p + 0.5f * (phi_p - phi * inv) * inv;
    float gs = g * inv;
    float fx = gs * x, fy = gs * y, fz = gs * z;
    atomicAdd(&forces[3*si],     fx);
    atomicAdd(&forces[3*si + 1], fy);
    atomicAdd(&forces[3*si + 2], fz);
    atomicAdd(&forces[3*di],    -fx);
    atomicAdd(&forces[3*di + 1],-fy);
    atomicAdd(&forces[3*di + 2],-fz);
}

__global__ void k_finalize(float* __restrict__ out) {
    out[0] = (float)g_E;
}

// ---------------- launch ------------------------------------------------------
extern "C" void kernel_launch(void* const* d_in, const int* in_sizes, int n_in,
                              void* d_out, int out_size) {
    const float* r    = (const float*)d_in[0];
    const int*   src  = (const int*)d_in[1];
    const int*   dst  = (const int*)d_in[2];
    const float* rs   = (const float*)d_in[4];
    const float* rhos = (const float*)d_in[5];
    const float* ra = (const float*)d_in[6];
    const float* rb = (const float*)d_in[7];
    const float* rc = (const float*)d_in[8];
    const float* rd = (const float*)d_in[9];
    const float* ea = (const float*)d_in[10];
    const float* eb = (const float*)d_in[11];
    const float* ec = (const float*)d_in[12];
    const float* ed = (const float*)d_in[13];
    float* out = (float*)d_out;
    int n_edges = in_sizes[0] / 3;

    const int T = 256;
    k_pack<<<(NR_C + T - 1) / T, T>>>(ra, rb, rc, rd, ea, eb, ec, ed);
    int zmax = max(out_size, N_NODES_C);
    k_zero<<<(zmax + T - 1) / T, T>>>(out, out_size);
    k_edge_rho<<<(n_edges + T - 1) / T, T>>>(r, dst, rs, n_edges);
    k_node<<<(N_NODES_C + T - 1) / T, T>>>(rhos);
    k_edge_force<<<(n_edges + T - 1) / T, T>>>(r, src, dst, rs, out + 1, n_edges);
    k_finalize<<<1, 1>>>(out);
}

// round 2
// speedup vs baseline: 2.0596x; 2.0596x over previous
#include <cuda_runtime.h>
#include <cuda_bf16.h>
#include <math.h>

// ---------------- problem constants (fixed shapes per reference) -------------
#define N_NODES_C 100000
#define NR_C      10000
#define NRHO_C    10000
#define CUTOFF_C  6.0f
#define RHOMAX_C  60.0f

// ---------------- device scratch (static, allocation-free) ------------------
__device__ float  g_node_rho[N_NODES_C];
__device__ float  g_Fp[N_NODES_C];
__device__ double g_E;
__device__ float4 g_force4[N_NODES_C];   // padded force accumulator (x,y,z,pad)
__device__ float4 g_rad0[NR_C - 1];      // density channel: a,b,c,d
__device__ float4 g_rad1[NR_C - 1];      // rphi channel:    a,b,c,d
__device__ float4 g_emb[NRHO_C - 1];     // embedding:       a,b,c,d

// ---------------- helpers ----------------------------------------------------
__device__ __forceinline__ int spline_idx(float x, const float* __restrict__ knots,
                                          int K, float scale) {
    int idx = (int)(x * scale);
    idx = min(max(idx, 0), K - 2);
    float k0 = __ldg(knots + idx);
    if (x < k0) {
        if (idx > 0) idx--;
    } else if (idx < K - 2 && x >= __ldg(knots + idx + 1)) {
        idx++;
    }
    return idx;
}

__device__ __forceinline__ void red_add_v4(float4* addr, float a, float b, float c, float d) {
    asm volatile("red.global.add.v4.f32 [%0], {%1, %2, %3, %4};"
                 :: "l"(addr), "f"(a), "f"(b), "f"(c), "f"(d) : "memory");
}

__device__ __forceinline__ double block_reduce_d(double v) {
    __shared__ double sh[32];
    #pragma unroll
    for (int o = 16; o > 0; o >>= 1) v += __shfl_down_sync(0xffffffffu, v, o);
    int lane = threadIdx.x & 31, w = threadIdx.x >> 5;
    if (lane == 0) sh[w] = v;
    __syncthreads();
    int nw = blockDim.x >> 5;
    v = (threadIdx.x < nw) ? sh[threadIdx.x] : 0.0;
    if (w == 0) {
        #pragma unroll
        for (int o = 16; o > 0; o >>= 1) v += __shfl_down_sync(0xffffffffu, v, o);
    }
    return v;
}

// ---------------- kernels ----------------------------------------------------
__global__ void k_pack(const float* __restrict__ ra, const float* __restrict__ rb,
                       const float* __restrict__ rc, const float* __restrict__ rd,
                       const float* __restrict__ ea, const float* __restrict__ eb,
                       const float* __restrict__ ec, const float* __restrict__ ed) {
    int i = blockIdx.x * blockDim.x + threadIdx.x;
    if (i < NR_C - 1) {
        g_rad0[i] = make_float4(ra[2*i],   rb[2*i],   rc[2*i],   rd[2*i]);
        g_rad1[i] = make_float4(ra[2*i+1], rb[2*i+1], rc[2*i+1], rd[2*i+1]);
    }
    if (i < NRHO_C - 1) {
        g_emb[i] = make_float4(ea[i], eb[i], ec[i], ed[i]);
    }
}

__global__ void k_zero() {
    int i = blockIdx.x * blockDim.x + threadIdx.x;
    if (i < N_NODES_C) {
        g_node_rho[i] = 0.0f;
        g_force4[i] = make_float4(0.0f, 0.0f, 0.0f, 0.0f);
    }
    if (i == 0) g_E = 0.0;
}

// Pass 1: per-edge density scatter + 0.5*sum(phi/r) into g_E
__global__ void k_edge_rho(const float* __restrict__ r,
                           const int* __restrict__ dst,
                           const float* __restrict__ rs,
                           int n_edges) {
    int e = blockIdx.x * blockDim.x + threadIdx.x;
    double part = 0.0;
    if (e < n_edges) {
        float x = r[3*e], y = r[3*e+1], z = r[3*e+2];
        float bl = sqrtf(x*x + y*y + z*z);
        int idx = spline_idx(bl, rs, NR_C, (float)(NR_C - 1) / CUTOFF_C);
        float s = bl - __ldg(rs + idx);
        float4 c0 = g_rad0[idx];
        float4 c1 = g_rad1[idx];
        float rho = c0.x + s * (c0.y + s * (c0.z + s * c0.w));
        float phi = c1.x + s * (c1.y + s * (c1.z + s * c1.w));
        atomicAdd(&g_node_rho[dst[e]], rho);
        part = 0.5 * (double)(phi / bl);
    }
    double tot = block_reduce_d(part);
    if (threadIdx.x == 0) atomicAdd(&g_E, tot);
}

// Pass 2: per-node embedding energy + derivative
__global__ void k_node(const float* __restrict__ rhos) {
    int n = blockIdx.x * blockDim.x + threadIdx.x;
    double part = 0.0;
    if (n < N_NODES_C) {
        float rho = g_node_rho[n];
        int idx = spline_idx(rho, rhos, NRHO_C, (float)(NRHO_C - 1) / RHOMAX_C);
        float s = rho - __ldg(rhos + idx);
        float4 c = g_emb[idx];
        float F  = c.x + s * (c.y + s * (c.z + s * c.w));
        float Fp = c.y + s * (2.0f * c.z + 3.0f * s * c.w);
        g_Fp[n] = Fp;
        part = (double)F;
    }
    double tot = block_reduce_d(part);
    if (threadIdx.x == 0) atomicAdd(&g_E, tot);
}

// Pass 3: per-edge force scatter (analytic gradient) via vector reductions
__global__ void k_edge_force(const float* __restrict__ r,
                             const int* __restrict__ src,
                             const int* __restrict__ dst,
                             const float* __restrict__ rs,
                             int n_edges) {
    int e = blockIdx.x * blockDim.x + threadIdx.x;
    if (e >= n_edges) return;
    float x = r[3*e], y = r[3*e+1], z = r[3*e+2];
    float bl = sqrtf(x*x + y*y + z*z);
    int idx = spline_idx(bl, rs, NR_C, (float)(NR_C - 1) / CUTOFF_C);
    float s = bl - __ldg(rs + idx);
    float4 c0 = g_rad0[idx];
    float4 c1 = g_rad1[idx];
    float rho_p = c0.y + s * (2.0f * c0.z + 3.0f * s * c0.w);
    float phi   = c1.x + s * (c1.y + s * (c1.z + s * c1.w));
    float phi_p = c1.y + s * (2.0f * c1.z + 3.0f * s * c1.w);
    int di = dst[e], si = src[e];
    float Fp = g_Fp[di];
    float inv = 1.0f / bl;
    float g = Fp * rho_p + 0.5f * (phi_p - phi * inv) * inv;   // dE/d|r|
    float gs = g * inv;
    float fx = gs * x, fy = gs * y, fz = gs * z;
    red_add_v4(&g_force4[si],  fx,  fy,  fz, 0.0f);
    red_add_v4(&g_force4[di], -fx, -fy, -fz, 0.0f);
}

// Final: out[0] = E, out[1 + 3n + c] = g_force4[n][c]  (coalesced elementwise)
__global__ void k_finalize(float* __restrict__ out, int n_force_elems) {
    int i = blockIdx.x * blockDim.x + threadIdx.x;
    if (i < n_force_elems) {
        int n = i / 3, c = i - 3 * n;
        const float* f = (const float*)&g_force4[n];
        out[1 + i] = f[c];
    }
    if (i == 0) out[0] = (float)g_E;
}

// ---------------- launch ------------------------------------------------------
extern "C" void kernel_launch(void* const* d_in, const int* in_sizes, int n_in,
                              void* d_out, int out_size) {
    const float* r    = (const float*)d_in[0];
    const int*   src  = (const int*)d_in[1];
    const int*   dst  = (const int*)d_in[2];
    const float* rs   = (const float*)d_in[4];
    const float* rhos = (const float*)d_in[5];
    const float* ra = (const float*)d_in[6];
    const float* rb = (const float*)d_in[7];
    const float* rc = (const float*)d_in[8];
    const float* rd = (const float*)d_in[9];
    const float* ea = (const float*)d_in[10];
    const float* eb = (const float*)d_in[11];
    const float* ec = (const float*)d_in[12];
    const float* ed = (const float*)d_in[13];
    float* out = (float*)d_out;
    int n_edges = in_sizes[0] / 3;

    const int T = 256;
    k_pack<<<(NR_C + T - 1) / T, T>>>(ra, rb, rc, rd, ea, eb, ec, ed);
    k_zero<<<(N_NODES_C + T - 1) / T, T>>>();
    k_edge_rho<<<(n_edges + T - 1) / T, T>>>(r, dst, rs, n_edges);
    k_node<<<(N_NODES_C + T - 1) / T, T>>>(rhos);
    k_edge_force<<<(n_edges + T - 1) / T, T>>>(r, src, dst, rs, n_edges);
    k_finalize<<<(out_size + T - 1) / T, T>>>(out, out_size - 1);
}